// round 1
// baseline (speedup 1.0000x reference)
#include <cuda_runtime.h>
#include <cstdint>

#define BB 256
#define PP 196
#define DD 512
#define AA 512
#define MM (BB*PP)   // 50176

// scratch (allocation-free rule: __device__ globals)
__device__ float g_hidden[BB*AA];   // hidden + bv, per (b,a)
__device__ float g_z[BB*PP];        // attention logits
__device__ float g_satt[BB];        // sentinel logit

__device__ __forceinline__ float tanh_fast(float x) {
    // tanh(x) = 1 - 2/(exp(2x)+1); robust at +-inf, ~1e-6 rel err with __expf
    float e = __expf(2.0f * x);
    return 1.0f - 2.0f / (e + 1.0f);
}

// ---------------------------------------------------------------------------
// K1: hidden[b,a] = dh[b,:]@Wh[:,a] + bh[a]   (stored with +bv[a] folded in)
//     s_att[b]   = sum_a tanh(st[b,:]@Ws[:,a] + bs[a] + hidden[b,a]) * Was[a] + bas
// grid 32 blocks x 256 threads, 8 batches per block, 2 a-columns per thread
// ---------------------------------------------------------------------------
__global__ void __launch_bounds__(256) k_prep(
    const float* __restrict__ dh, const float* __restrict__ st,
    const float* __restrict__ Wh, const float* __restrict__ bh,
    const float* __restrict__ Ws, const float* __restrict__ bs,
    const float* __restrict__ Was, const float* __restrict__ bas,
    const float* __restrict__ bv)
{
    __shared__ float dh_s[8*DD];
    __shared__ float st_s[8*DD];
    __shared__ float s_part[8];
    const int tid = threadIdx.x;
    const int b0  = blockIdx.x * 8;

    for (int i = tid; i < 8*DD; i += 256) {
        int b = i >> 9, d = i & 511;
        dh_s[i] = dh[(b0 + b)*DD + d];
        st_s[i] = st[(b0 + b)*DD + d];
    }
    if (tid < 8) s_part[tid] = 0.f;
    __syncthreads();

    for (int aa = 0; aa < 2; ++aa) {
        const int a = tid + aa*256;
        float acch[8], accs[8];
        const float bha = bh[a], bsa = bs[a];
        #pragma unroll
        for (int b = 0; b < 8; ++b) { acch[b] = bha; accs[b] = bsa; }

        #pragma unroll 4
        for (int d = 0; d < DD; ++d) {
            const float wh = Wh[d*AA + a];
            const float ws = Ws[d*AA + a];
            #pragma unroll
            for (int b = 0; b < 8; ++b) {
                acch[b] += dh_s[b*DD + d] * wh;
                accs[b] += st_s[b*DD + d] * ws;
            }
        }
        const float was = Was[a], bva = bv[a];
        #pragma unroll
        for (int b = 0; b < 8; ++b) {
            const float h = acch[b];
            g_hidden[(size_t)(b0 + b)*AA + a] = h + bva;
            float t = tanh_fast(accs[b] + h) * was;
            #pragma unroll
            for (int off = 16; off; off >>= 1)
                t += __shfl_xor_sync(0xffffffffu, t, off);
            if ((tid & 31) == 0) atomicAdd(&s_part[b], t);
        }
    }
    __syncthreads();
    if (tid < 8) g_satt[b0 + tid] = s_part[tid] + bas[0];
}

// ---------------------------------------------------------------------------
// K2: fused  z[m] = bav + sum_a Wav[a] * tanh( enc[m,:]@Wv[:,a] + hidden[b(m),a] )
// 64 M-rows per block, N looped in 8 tiles of 64, K staged in 16-chunks.
// 256 threads, 4x4 microtile (tx = n-group 0..15, ty = m-group 0..15).
// ---------------------------------------------------------------------------
__global__ void __launch_bounds__(256) k_zgemm(
    const float* __restrict__ enc, const float* __restrict__ Wv,
    const float* __restrict__ Wav, const float* __restrict__ bav)
{
    __shared__ __align__(16) float A_s[16*68];   // [k][r], padded row stride 68
    __shared__ __align__(16) float B_s[16*64];   // [k][n]
    __shared__ __align__(16) float wav_s[AA];
    __shared__ float zs[64];

    const int tid = threadIdx.x;
    const int m0  = blockIdx.x * 64;
    const int tx  = tid & 15;    // n-group
    const int ty  = tid >> 4;    // m-group

    for (int i = tid; i < AA; i += 256) wav_s[i] = Wav[i];
    if (tid < 64) zs[tid] = 0.f;

    for (int nt = 0; nt < 8; ++nt) {
        const int n0 = nt * 64;
        float acc[4][4];
        #pragma unroll
        for (int r = 0; r < 4; ++r)
            #pragma unroll
            for (int c = 0; c < 4; ++c) acc[r][c] = 0.f;

        float pa[4], pb[4];
        #pragma unroll
        for (int j = 0; j < 4; ++j) {       // prefetch kb=0
            const int i = tid + 256*j;
            pa[j] = enc[(size_t)(m0 + (i >> 4))*DD + (i & 15)];
            pb[j] = Wv[(size_t)(i >> 6)*AA + n0 + (i & 63)];
        }

        for (int kb = 0; kb < DD; kb += 16) {
            __syncthreads();                 // previous stage consumed / zs init
            #pragma unroll
            for (int j = 0; j < 4; ++j) {
                const int i = tid + 256*j;
                A_s[(i & 15)*68 + (i >> 4)] = pa[j];
                B_s[i] = pb[j];
            }
            __syncthreads();
            if (kb + 16 < DD) {
                #pragma unroll
                for (int j = 0; j < 4; ++j) {
                    const int i = tid + 256*j;
                    pa[j] = enc[(size_t)(m0 + (i >> 4))*DD + kb + 16 + (i & 15)];
                    pb[j] = Wv[(size_t)(kb + 16 + (i >> 6))*AA + n0 + (i & 63)];
                }
            }
            #pragma unroll
            for (int kk = 0; kk < 16; ++kk) {
                const float4 a4 = *reinterpret_cast<const float4*>(&A_s[kk*68 + 4*ty]);
                const float4 b4 = *reinterpret_cast<const float4*>(&B_s[kk*64 + 4*tx]);
                const float av[4] = {a4.x, a4.y, a4.z, a4.w};
                const float bw[4] = {b4.x, b4.y, b4.z, b4.w};
                #pragma unroll
                for (int r = 0; r < 4; ++r)
                    #pragma unroll
                    for (int c = 0; c < 4; ++c)
                        acc[r][c] += av[r] * bw[c];
            }
        }

        // epilogue: tanh(v + hidden) * Wav, reduce over the 64 n's of this tile
        float rsum[4];
        #pragma unroll
        for (int r = 0; r < 4; ++r) {
            const int m = m0 + 4*ty + r;
            const int b = m / PP;
            const float4 h4 = *reinterpret_cast<const float4*>(
                &g_hidden[(size_t)b*AA + n0 + 4*tx]);
            const float hv[4] = {h4.x, h4.y, h4.z, h4.w};
            float s = 0.f;
            #pragma unroll
            for (int c = 0; c < 4; ++c)
                s += tanh_fast(acc[r][c] + hv[c]) * wav_s[n0 + 4*tx + c];
            rsum[r] = s;
        }
        #pragma unroll
        for (int off = 8; off; off >>= 1)
            #pragma unroll
            for (int r = 0; r < 4; ++r)
                rsum[r] += __shfl_xor_sync(0xffffffffu, rsum[r], off);
        if (tx == 0) {
            #pragma unroll
            for (int r = 0; r < 4; ++r) zs[4*ty + r] += rsum[r];   // unique owner
        }
    }
    __syncthreads();
    if (tid < 64) g_z[m0 + tid] = zs[tid] + bav[0];
}

// ---------------------------------------------------------------------------
// K3: softmax(z) -> alpha ; extended softmax with s_att -> beta ;
//     c_t = enc^T alpha ; c_hat = beta*st + (1-beta)*c_t
// grid (B, 2): each block owns 256 of the 512 d's of batch b.
// ---------------------------------------------------------------------------
__global__ void __launch_bounds__(256) k_soft(
    const float* __restrict__ enc, const float* __restrict__ st,
    float* __restrict__ out)
{
    __shared__ float zsh[PP];
    __shared__ float alpha_sh[PP];
    __shared__ float red[256];
    const int tid = threadIdx.x;
    const int b   = blockIdx.x;
    const int y   = blockIdx.y;

    if (tid < PP) zsh[tid] = g_z[b*PP + tid];
    __syncthreads();

    // max over 196
    red[tid] = (tid < PP) ? zsh[tid] : -1e30f;
    __syncthreads();
    for (int s = 128; s > 0; s >>= 1) {
        if (tid < s) red[tid] = fmaxf(red[tid], red[tid + s]);
        __syncthreads();
    }
    const float m1 = red[0];
    __syncthreads();

    // sum exp
    const float e = (tid < PP) ? __expf(zsh[tid] - m1) : 0.f;
    red[tid] = e;
    __syncthreads();
    for (int s = 128; s > 0; s >>= 1) {
        if (tid < s) red[tid] += red[tid + s];
        __syncthreads();
    }
    const float sum1 = red[0];

    if (tid < PP) {
        const float alpha = e / sum1;
        alpha_sh[tid] = alpha;
        if (y == 0) out[BB*DD + b*PP + tid] = alpha;   // alpha_t
    }

    const float sa   = g_satt[b];
    const float m2   = fmaxf(m1, sa);
    const float sum2 = sum1 * __expf(m1 - m2) + __expf(sa - m2);
    const float beta = __expf(sa - m2) / sum2;
    if (y == 0 && tid == 0) out[BB*DD + BB*PP + b] = beta;  // beta_t
    __syncthreads();

    // c_t for this thread's d
    const int d = y*256 + tid;
    const float* ep = enc + (size_t)b*PP*DD + d;
    float acc = 0.f;
    #pragma unroll 4
    for (int p = 0; p < PP; ++p)
        acc += ep[(size_t)p*DD] * alpha_sh[p];

    out[b*DD + d] = beta * st[b*DD + d] + (1.f - beta) * acc;  // c_hat_t
}

// ---------------------------------------------------------------------------
extern "C" void kernel_launch(void* const* d_in, const int* in_sizes, int n_in,
                              void* d_out, int out_size) {
    const float* enc = (const float*)d_in[0];
    const float* dh  = (const float*)d_in[1];
    const float* st  = (const float*)d_in[2];
    const float* Wv  = (const float*)d_in[3];
    const float* bv  = (const float*)d_in[4];
    const float* Wh  = (const float*)d_in[5];
    const float* bh  = (const float*)d_in[6];
    const float* Ws  = (const float*)d_in[7];
    const float* bs  = (const float*)d_in[8];
    const float* Wav = (const float*)d_in[9];
    const float* bav = (const float*)d_in[10];
    const float* Was = (const float*)d_in[11];
    const float* bas = (const float*)d_in[12];
    float* out = (float*)d_out;

    k_prep <<<32, 256>>>(dh, st, Wh, bh, Ws, bs, Was, bas, bv);
    k_zgemm<<<MM/64, 256>>>(enc, Wv, Wav, bav);
    k_soft <<<dim3(BB, 2), 256>>>(enc, st, out);
}